// round 13
// baseline (speedup 1.0000x reference)
#include <cuda_runtime.h>
#include <math.h>

#define B   32
#define E   512
#define H   512
#define H4  2048
#define S   64
#define T   48
#define VT  32000
#define TL  (T-1)
#define VB  640
#define NCHUNK (VT/VB)
#define NBLK 128

#define PIDX(h,b) ((((h)>>1)<<6) + ((b)<<1) + ((h)&1))
typedef unsigned long long ull;

__device__ __align__(128) float g_x[S*E*B];
__device__ __align__(128) float g_y[T*E*B];
__device__ __align__(128) float g_zx0[S*H4*B];
__device__ __align__(128) float g_zy [T*H4*B];
__device__ __align__(128) float g_h1seq[S*H*B];
__device__ __align__(128) float g_h2seq[S*H*B];
__device__ __align__(128) float g_ebsh[B*S*H];
__device__ __align__(128) float g_ebhs[B*H*S];
__device__ __align__(128) float g_F[B*H*S];
__device__ __align__(128) float g_A[H*B];
__device__ __align__(128) float g_zcy[H*B];
__device__ __align__(128) float g_scores[B*S];
__device__ __align__(128) float g_c0[H*B];
__device__ __align__(128) float g_c1[H*B];
__device__ __align__(128) float g_dh0a[H*B];
__device__ __align__(128) float g_dh0b[H*B];
__device__ __align__(128) float g_dh1a[H*B];
__device__ __align__(128) float g_dh1b[H*B];
__device__ __align__(128) float g_zero[H*B];
__device__ __align__(128) float g_decout[T*H*B];
__device__ __align__(128) float g_pmax[TL*NCHUNK*B];
__device__ __align__(128) float g_psum[TL*NCHUNK*B];
__device__ __align__(128) float g_tgtl[TL*B];
__device__ __align__(128) float g_lp[TL*B];

__device__ __forceinline__ void fma2(ull& a, ull w, ull u) {
    asm("fma.rn.f32x2 %0, %1, %2, %3;" : "=l"(a) : "l"(w), "l"(u), "l"(a));
}
__device__ __forceinline__ float sum2(ull v) {
    float lo, hi;
    asm("mov.b64 {%0, %1}, %2;" : "=f"(lo), "=f"(hi) : "l"(v));
    return lo + hi;
}
// L2-direct loads (cannot hit stale L1; needed because barriers no longer flush L1)
__device__ __forceinline__ ull ldcg64(const float* p) {
    ull v; asm volatile("ld.global.cg.b64 %0, [%1];" : "=l"(v) : "l"(p)); return v;
}
__device__ __forceinline__ float ldcgf(const float* p) {
    float v; asm volatile("ld.global.cg.f32 %0, [%1];" : "=f"(v) : "l"(p)); return v;
}

// ---- fence-free grid barrier: acq_rel atomics at L2, no CCTL.IVALL ----
__device__ unsigned g_cnt0, g_gen0, g_cnt1, g_gen1, g_cntD, g_genD;

__device__ __forceinline__ unsigned atom_arrive(unsigned* p) {
    unsigned old;
    asm volatile("atom.acq_rel.gpu.global.add.u32 %0, [%1], 1;"
                 : "=r"(old) : "l"(p) : "memory");
    return old;
}
__device__ __forceinline__ void st_rel(unsigned* p, unsigned v) {
    asm volatile("st.release.gpu.global.u32 [%0], %1;" :: "l"(p), "r"(v) : "memory");
}
__device__ __forceinline__ unsigned ld_cg_u(const unsigned* p) {
    unsigned v;
    asm volatile("ld.global.cg.u32 %0, [%1];" : "=r"(v) : "l"(p) : "memory");
    return v;
}
__device__ __forceinline__ void pbar(unsigned* cnt, unsigned* gen, unsigned n) {
    __syncthreads();
    if (threadIdx.x == 0) {
        unsigned old = ld_cg_u(gen);
        unsigned a = atom_arrive(cnt);
        if (a == n - 1) {
            *(volatile unsigned*)cnt = 0;
            st_rel(gen, old + 1);        // release orders cnt-reset + all prior STG
        } else {
            while (ld_cg_u(gen) == old) __nanosleep(32);
        }
    }
    __syncthreads();
}
__device__ __forceinline__ void wait_ge(const unsigned* gen, unsigned target) {
    __syncthreads();
    if (threadIdx.x == 0)
        while (ld_cg_u(gen) < target) __nanosleep(32);
    __syncthreads();
}

__global__ void k_setup() {
    int i = blockIdx.x * 256 + threadIdx.x;
    if (i < H * B) { g_c0[i] = 0.f; g_c1[i] = 0.f; g_zero[i] = 0.f; }
    if (i == 0) {
        g_cnt0 = 0; g_gen0 = 0; g_cnt1 = 0; g_gen1 = 0; g_cntD = 0; g_genD = 0;
    }
}

__global__ void k_embed2(const int* __restrict__ src, const int* __restrict__ tgt,
                         const float* __restrict__ semb, const float* __restrict__ temb) {
    int n = blockIdx.x, b = blockIdx.y;
    const float* e; float* d;
    if (n < S) { e = semb + (size_t)src[n * B + b] * E; d = g_x + (size_t)n * E * B; }
    else { int m = n - S; e = temb + (size_t)tgt[m * B + b] * E; d = g_y + (size_t)m * E * B; }
    for (int k = threadIdx.x; k < E; k += 128) d[PIDX(k, b)] = e[k];
}

// both pre-GEMMs, no smem, 2 timesteps per block. grid (32, 56).
__global__ void __launch_bounds__(256) k_gemm_pre2(
        const float* __restrict__ Wx, const float* __restrict__ bx,
        const float* __restrict__ Wy, const float* __restrict__ by_) {
    const int tid = threadIdx.x, lane = tid & 31, warp = tid >> 5;
    const int by = blockIdx.y;
    const float *W, *bias, *U; float* Z; int ldw, n0;
    if (by < 32) { W = Wx; bias = bx;  U = g_x; Z = g_zx0; ldw = E;     n0 = by * 2; }
    else         { W = Wy; bias = by_; U = g_y; Z = g_zy;  ldw = E + H; n0 = (by - 32) * 2; }
    const int o0 = blockIdx.x * 64 + warp * 8;
    const float* u0 = U + (size_t)n0 * 512 * B;
    const float* u1 = U + (size_t)(n0 + 1) * 512 * B;
    ull acc[8][2];
    #pragma unroll
    for (int r = 0; r < 8; r++) { acc[r][0] = 0ull; acc[r][1] = 0ull; }
    #pragma unroll 4
    for (int k = 0; k < 512; k += 4) {
        const int ko = (k >> 1) * 64 + lane * 2;
        ull a01 = *(const ull*)(u0 + ko), a23 = *(const ull*)(u0 + ko + 64);
        ull b01 = *(const ull*)(u1 + ko), b23 = *(const ull*)(u1 + ko + 64);
        #pragma unroll
        for (int r = 0; r < 8; r++) {
            ulonglong2 wv = *(const ulonglong2*)(W + (size_t)(o0 + r) * ldw + k);
            fma2(acc[r][0], wv.x, a01); fma2(acc[r][0], wv.y, a23);
            fma2(acc[r][1], wv.x, b01); fma2(acc[r][1], wv.y, b23);
        }
    }
    #pragma unroll
    for (int r = 0; r < 8; r++) {
        float bv = bias[o0 + r];
        Z[((size_t)n0 * H4 + o0 + r) * B + lane]       = sum2(acc[r][0]) + bv;
        Z[((size_t)(n0 + 1) * H4 + o0 + r) * B + lane] = sum2(acc[r][1]) + bv;
    }
}

// LSTM cell, zero-staging: u via coalesced LDG.cg (pair-packed), weights in SMEM.
template<int HPB, bool DUAL>
__device__ __forceinline__ void cellK(
        int blk, const float* __restrict__ zpre, const float* __restrict__ bias,
        const float* sW1, const float* sW2,
        const float* __restrict__ u1, const float* __restrict__ u2,
        float* __restrict__ C, float* __restrict__ Hout, float* sz) {
    const int tid = threadIdx.x, lane = tid & 31, w = tid >> 5;
    int m, ksl, rg, kstart, klen;
    if (DUAL) {
        m = w >> 3; int wm = w & 7;
        if (HPB == 4) { ksl = wm >> 1; rg = wm & 1; kstart = ksl * 128; klen = 128; }
        else          { ksl = wm >> 2; rg = wm & 3; kstart = ksl * 256; klen = 256; }
    } else { m = 0; ksl = w >> 2; rg = w & 3; kstart = ksl * 128; klen = 128; }
    const float* u  = (DUAL && m) ? u2  : u1;
    const float* sW = (DUAL && m) ? sW2 : sW1;
    const float* sWr = sW + rg * 8 * 512;
    ull acc[8][2];
    #pragma unroll
    for (int j = 0; j < 8; j++) { acc[j][0] = 0ull; acc[j][1] = 0ull; }
    #pragma unroll 4
    for (int k = kstart; k < kstart + klen; k += 4) {
        const int ko = (k >> 1) * 64 + lane * 2;
        ull u01 = ldcg64(u + ko);
        ull u23 = ldcg64(u + ko + 64);
        #pragma unroll
        for (int j = 0; j < 8; j++) {
            ulonglong2 wv = *(const ulonglong2*)(sWr + j * 512 + k);
            fma2(acc[j][0], wv.x, u01);
            fma2(acc[j][1], wv.y, u23);
        }
    }
    #pragma unroll
    for (int j = 0; j < 8; j++)
        sz[(w * 8 + j) * 32 + lane] = sum2(acc[j][0]) + sum2(acc[j][1]);
    __syncthreads();
    if (tid < HPB * 32) {
        int hh = tid >> 5, b = tid & 31;
        float z[4];
        #pragma unroll
        for (int gate = 0; gate < 4; gate++) {
            int r = gate * HPB + hh;
            int o = gate * H + blk * HPB + hh;
            float v = zpre ? zpre[(size_t)o * B + b] : bias[o];
            int rgr = r >> 3, jj = r & 7;
            if (DUAL) {
                if (HPB == 4) {
                    #pragma unroll
                    for (int m2 = 0; m2 < 2; m2++)
                        #pragma unroll
                        for (int k2 = 0; k2 < 4; k2++)
                            v += sz[((m2 * 8 + k2 * 2 + rgr) * 8 + jj) * 32 + b];
                } else {
                    #pragma unroll
                    for (int m2 = 0; m2 < 2; m2++)
                        #pragma unroll
                        for (int k2 = 0; k2 < 2; k2++)
                            v += sz[((m2 * 8 + k2 * 4 + rgr) * 8 + jj) * 32 + b];
                }
            } else {
                #pragma unroll
                for (int k2 = 0; k2 < 4; k2++)
                    v += sz[((k2 * 4 + rgr) * 8 + jj) * 32 + b];
            }
            z[gate] = v;
        }
        float ig = 1.f / (1.f + expf(-z[0]));
        float fg = 1.f / (1.f + expf(-z[1]));
        float gg = tanhf(z[2]);
        float og = 1.f / (1.f + expf(-z[3]));
        int h = blk * HPB + hh;
        float c2 = fg * C[h * B + b] + ig * gg;
        C[h * B + b]     = c2;
        Hout[PIDX(h, b)] = og * tanhf(c2);
    }
    __syncthreads();
}

// encoder: layer0 on blocks 0-63 (own 64-barrier), layer1 on 64-127 follows
// layer0's generation counter one step behind (one-way wait).
__global__ void __launch_bounds__(512) k_encoder(
        const float* __restrict__ eWhh0, const float* __restrict__ eWih1,
        const float* __restrict__ eWhh1, const float* __restrict__ eb1) {
    extern __shared__ __align__(16) float sm[];
    float* sz = sm;            // 4096 floats
    float* sw = sm + 4096;     // up to 32768 floats
    const int blk = blockIdx.x, tid = threadIdx.x;
    if (blk < 64) {
        for (int i = tid; i < 32 * 128; i += 512) {
            int r = i >> 7, c4 = i & 127;
            int o = (r >> 3) * H + blk * 8 + (r & 7);
            ((float4*)sw)[i] = *(const float4*)(eWhh0 + (size_t)o * H + c4 * 4);
        }
        __syncthreads();
        for (int s = 0; s < S; s++) {
            const float* hp = s ? g_h1seq + (size_t)(s - 1) * H * B : g_zero;
            cellK<8, false>(blk, g_zx0 + (size_t)s * H4 * B, nullptr, sw, nullptr,
                            hp, nullptr, g_c0, g_h1seq + (size_t)s * H * B, sz);
            pbar(&g_cnt0, &g_gen0, 64);
        }
    } else {
        int b2 = blk - 64;
        for (int i = tid; i < 32 * 128; i += 512) {
            int r = i >> 7, c4 = i & 127;
            int o = (r >> 3) * H + b2 * 8 + (r & 7);
            ((float4*)sw)[i]           = *(const float4*)(eWih1 + (size_t)o * H + c4 * 4);
            ((float4*)(sw + 16384))[i] = *(const float4*)(eWhh1 + (size_t)o * H + c4 * 4);
        }
        __syncthreads();
        for (int s = 0; s < S; s++) {
            wait_ge(&g_gen0, (unsigned)(s + 1));   // h1seq[s] ready
            const float* hp = s ? g_h2seq + (size_t)(s - 1) * H * B : g_zero;
            cellK<8, true>(b2, nullptr, eb1, sw, sw + 16384,
                           g_h1seq + (size_t)s * H * B, hp,
                           g_c1, g_h2seq + (size_t)s * H * B, sz);
            pbar(&g_cnt1, &g_gen1, 64);
        }
        // transpose encode_h (group1 only; its barrier covers all h2seq writes)
        for (int idx = b2; idx < S * B; idx += 64) {
            int s = idx >> 5, b = idx & 31;
            for (int h = tid; h < H; h += 512) {
                float v = ldcgf(g_h2seq + (size_t)s * H * B + PIDX(h, b));
                g_ebsh[((size_t)b * S + s) * H + h] = v;
                g_ebhs[((size_t)b * H + h) * S + s] = v;
            }
        }
    }
}

// F[b,h,s] = sum_k Wct[h,k] * ebhs[b,k,s]
__global__ void __launch_bounds__(256) k_Fpre(const float* __restrict__ Wct) {
    extern __shared__ __align__(16) float smf[];
    float* se  = smf;
    float* swd = smf + 8192;
    const ull* se2  = (const ull*)se;
    const ull* swd2 = (const ull*)swd;
    const int tid = threadIdx.x, lane = tid & 31, w = tid >> 5;
    const int hc = blockIdx.x, b = blockIdx.y;
    ull acc2[8] = {0ull,0ull,0ull,0ull,0ull,0ull,0ull,0ull};
    for (int kc = 0; kc < 4; kc++) {
        __syncthreads();
        {
            const float4* src = (const float4*)(g_ebhs + ((size_t)b * H + kc * 128) * S);
            #pragma unroll
            for (int i = tid; i < 2048; i += 256) ((float4*)se)[i] = src[i];
            #pragma unroll
            for (int i4 = tid; i4 < 2048; i4 += 256) {
                int row = i4 >> 5, c4 = i4 & 31;
                float4 v = *(const float4*)(Wct + (size_t)(hc * 64 + row) * 1024 + kc * 128 + c4 * 4);
                float2* dp = (float2*)(swd + (row * 128 + c4 * 4) * 2);
                dp[0] = make_float2(v.x, v.x); dp[1] = make_float2(v.y, v.y);
                dp[2] = make_float2(v.z, v.z); dp[3] = make_float2(v.w, v.w);
            }
        }
        __syncthreads();
        #pragma unroll 4
        for (int kk = 0; kk < 128; kk++) {
            ull u = se2[kk * 32 + lane];
            #pragma unroll
            for (int r = 0; r < 8; r++)
                fma2(acc2[r], swd2[(w * 8 + r) * 128 + kk], u);
        }
    }
    #pragma unroll
    for (int r = 0; r < 8; r++) {
        int h = hc * 64 + w * 8 + r;
        ((ull*)(g_F + ((size_t)b * H + h) * S))[lane] = acc2[r];
    }
}

__global__ void __launch_bounds__(512) k_decoder(
        const float* __restrict__ dWih0, const float* __restrict__ dWhh0,
        const float* __restrict__ dWih1, const float* __restrict__ dWhh1,
        const float* __restrict__ db1,
        const float* __restrict__ Wht, const float* __restrict__ Wpt,
        const float* __restrict__ Wct, const int* __restrict__ elen) {
    extern __shared__ __align__(16) float sm[];
    float* sz  = sm;            // 4096
    float* sWa = sm + 4096;     // 4 x 8192
    float* sWb = sWa + 8192;
    float* sWc = sWb + 8192;
    float* sWd = sWc + 8192;
    float* sy  = sWd + 8192;    // 512
    __shared__ float s_at[S];
    __shared__ float s_red[20];
    const int blk = blockIdx.x, tid = threadIdx.x, lane = tid & 31, w = tid >> 5;
    for (int i = tid; i < 2048; i += 512) {
        int r = i >> 7, c4 = i & 127;
        int o = (r >> 2) * H + blk * 4 + (r & 3);
        ((float4*)sWa)[i] = *(const float4*)(dWih0 + (size_t)o * (E + H) + E + c4 * 4);
        ((float4*)sWb)[i] = *(const float4*)(dWhh0 + (size_t)o * H + c4 * 4);
        ((float4*)sWc)[i] = *(const float4*)(dWih1 + (size_t)o * H + c4 * 4);
        ((float4*)sWd)[i] = *(const float4*)(dWhh1 + (size_t)o * H + c4 * 4);
    }
    __syncthreads();
    for (int t = 0; t < T; t++) {
        const float* htp = t ? g_decout + (size_t)(t - 1) * H * B : g_zero;
        const float* h0p = t ? (((t - 1) & 1) ? g_dh0b : g_dh0a)
                             : g_h1seq + (size_t)(S - 1) * H * B;
        float* h0c = (t & 1) ? g_dh0b : g_dh0a;
        cellK<4, true>(blk, g_zy + (size_t)t * H4 * B, nullptr, sWa, sWb,
                       htp, h0p, g_c0, h0c, sz);
        pbar(&g_cntD, &g_genD, NBLK);
        const float* h1p = t ? (((t - 1) & 1) ? g_dh1b : g_dh1a)
                             : g_h2seq + (size_t)(S - 1) * H * B;
        float* h1c = (t & 1) ? g_dh1b : g_dh1a;
        cellK<4, true>(blk, nullptr, db1, sWc, sWd, h0c, h1p, g_c1, h1c, sz);
        pbar(&g_cntD, &g_genD, NBLK);
        // P3: distributed GEMV (A rows + zcy rows) + scores on blocks 0-31
        {
            if (blk < B) sy[tid] = ldcgf(h1c + PIDX(tid, blk));
            {
                int j = w >> 1, khalf = w & 1;
                int rid = blk * 8 + j;
                const float* Wrow = (rid < 512) ? (Wht + (size_t)rid * 512)
                                                : (Wct + (size_t)(rid - 512) * 1024 + 512);
                ull a0 = 0ull, a1 = 0ull;
                const int kb = khalf * 256;
                #pragma unroll 4
                for (int kk = 0; kk < 256; kk += 4) {
                    const int k = kb + kk;
                    const int ko = (k >> 1) * 64 + lane * 2;
                    ull u01 = ldcg64(h1c + ko);
                    ull u23 = ldcg64(h1c + ko + 64);
                    ulonglong2 wv = *(const ulonglong2*)(Wrow + k);
                    fma2(a0, wv.x, u01);
                    fma2(a1, wv.y, u23);
                }
                sz[w * 32 + lane] = sum2(a0) + sum2(a1);
            }
            __syncthreads();
            if (tid < 256) {
                int jj = tid >> 5, b = tid & 31;
                int rr = blk * 8 + jj;
                float v = sz[(2 * jj) * 32 + b] + sz[(2 * jj + 1) * 32 + b];
                if (rr < 512) g_A[rr * 32 + b] = Wpt[rr] * tanhf(v);
                else          g_zcy[(rr - 512) * 32 + b] = v;
            }
            if (blk < B) {
                int b = blk, el = elen[b];
                float4 uk[4];
                #pragma unroll
                for (int qq = 0; qq < 4; qq++) uk[qq] = *(const float4*)(sy + qq * 128 + lane * 4);
                #pragma unroll
                for (int si = 0; si < 4; si++) {
                    int s = w * 4 + si;
                    const float* er = g_ebsh + ((size_t)b * S + s) * H;
                    float v = 0.f;
                    #pragma unroll
                    for (int qq = 0; qq < 4; qq++) {
                        float4 ev = *(const float4*)(er + qq * 128 + lane * 4);
                        v += ev.x*uk[qq].x + ev.y*uk[qq].y + ev.z*uk[qq].z + ev.w*uk[qq].w;
                    }
                    #pragma unroll
                    for (int off = 16; off; off >>= 1)
                        v += __shfl_xor_sync(0xffffffffu, v, off);
                    if (lane == 0) g_scores[b * S + s] = (s < el) ? v : -INFINITY;
                }
            }
        }
        pbar(&g_cntD, &g_genD, NBLK);
        // P4: pt + softmax*gauss + decout (blocks 0-31)
        if (blk < B) {
            int b = blk;
            float a = ldcgf(g_A + tid * 32 + b);
            #pragma unroll
            for (int off = 16; off; off >>= 1) a += __shfl_xor_sync(0xffffffffu, a, off);
            if (lane == 0) s_red[w] = a;
            __syncthreads();
            if (tid == 0) {
                float dd = 0.f;
                #pragma unroll
                for (int i = 0; i < 16; i++) dd += s_red[i];
                s_red[16] = (1.f / (1.f + expf(-dd))) * (float)elen[b];
            }
            __syncthreads();
            if (w == 0) {
                float pt = s_red[16];
                float v0 = g_scores[b * S + lane], v1 = g_scores[b * S + lane + 32];
                float mx = fmaxf(v0, v1);
                #pragma unroll
                for (int off = 16; off; off >>= 1)
                    mx = fmaxf(mx, __shfl_xor_sync(0xffffffffu, mx, off));
                float e0 = expf(v0 - mx), e1 = expf(v1 - mx);
                float smv = e0 + e1;
                #pragma unroll
                for (int off = 16; off; off >>= 1)
                    smv += __shfl_xor_sync(0xffffffffu, smv, off);
                float inv = 1.f / smv;
                float d0 = (float)lane - pt, d1 = (float)(lane + 32) - pt;
                s_at[lane]      = e0 * inv * expf(-d0 * d0 * (1.f / 50.f));
                s_at[lane + 32] = e1 * inv * expf(-d1 * d1 * (1.f / 50.f));
            }
            __syncthreads();
            {
                int h = tid;
                float f = ldcgf(g_zcy + h * 32 + b);
                const float4* Fr = (const float4*)(g_F + ((size_t)b * H + h) * S);
                #pragma unroll
                for (int s4 = 0; s4 < 16; s4++) {
                    float4 fv = Fr[s4];
                    f += s_at[s4*4+0]*fv.x + s_at[s4*4+1]*fv.y
                       + s_at[s4*4+2]*fv.z + s_at[s4*4+3]*fv.w;
                }
                g_decout[(size_t)t * H * B + PIDX(h, b)] = tanhf(f);
            }
        }
        pbar(&g_cntD, &g_genD, NBLK);
    }
}

__global__ void __launch_bounds__(256) k_logits(const float* __restrict__ Wf,
                                                const int* __restrict__ target) {
    extern __shared__ __align__(16) float sm_[];
    float* sdec = sm_;
    float* wt   = sm_ + 512 * B;
    const ull* sd2 = (const ull*)sdec;
    __shared__ float rm[8][32], rs[8][32];
    const int t = blockIdx.y, c = blockIdx.x;
    const int tid = threadIdx.x, lane = tid & 31, warp = tid >> 5;
    {
        const float4* src = (const float4*)&g_decout[(size_t)t * H * B];
        #pragma unroll
        for (int i = tid; i < H * B / 4; i += 256) ((float4*)sdec)[i] = src[i];
    }
    __syncthreads();
    const int tgt = target[(t + 1) * B + lane];
    float m = -INFINITY, ss = 0.f;
    for (int rt = 0; rt < 10; rt++) {
        const int r0 = c * VB + rt * 64;
        ull acc2[8] = {0ull,0ull,0ull,0ull,0ull,0ull,0ull,0ull};
        for (int kc = 0; kc < 4; kc++) {
            __syncthreads();
            #pragma unroll
            for (int q = 0; q < 8; q++) {
                int f4 = q * 256 + tid;
                ((float4*)wt)[f4] = *(const float4*)(
                    Wf + (size_t)(r0 + (f4 >> 5)) * H + kc * 128 + (f4 & 31) * 4);
            }
            __syncthreads();
            const ull* ub2 = sd2 + kc * 2048;
            #pragma unroll 4
            for (int kk = 0; kk < 128; kk += 4) {
                ull u01 = ub2[(kk >> 1) * 32 + lane];
                ull u23 = ub2[(kk >> 1) * 32 + 32 + lane];
                #pragma unroll
                for (int r = 0; r < 8; r++) {
                    ulonglong2 wv = *(const ulonglong2*)(wt + (warp * 8 + r) * 128 + kk);
                    fma2(acc2[r], wv.x, u01);
                    fma2(acc2[r], wv.y, u23);
                }
            }
        }
        #pragma unroll
        for (int r = 0; r < 8; r++) {
            float x = sum2(acc2[r]);
            if (r0 + warp * 8 + r == tgt) g_tgtl[t * B + lane] = x;
            float nm = fmaxf(m, x);
            ss = ss * expf(m - nm) + expf(x - nm);
            m = nm;
        }
    }
    rm[warp][lane] = m; rs[warp][lane] = ss;
    __syncthreads();
    if (tid < 32) {
        float M = -INFINITY, SS = 0.f;
        #pragma unroll
        for (int w2 = 0; w2 < 8; w2++) {
            float wm = rm[w2][tid], wss = rs[w2][tid];
            float nm = fmaxf(M, wm);
            SS = SS * expf(M - nm) + wss * expf(wm - nm);
            M = nm;
        }
        g_pmax[((size_t)t * NCHUNK + c) * B + tid] = M;
        g_psum[((size_t)t * NCHUNK + c) * B + tid] = SS;
    }
}

__global__ void k_combine(const int* __restrict__ target) {
    const int t = blockIdx.x, b = threadIdx.x;
    float M = -INFINITY;
    for (int c = 0; c < NCHUNK; c++)
        M = fmaxf(M, g_pmax[((size_t)t * NCHUNK + c) * B + b]);
    float ss = 0.f;
    for (int c = 0; c < NCHUNK; c++)
        ss += g_psum[((size_t)t * NCHUNK + c) * B + b] *
              expf(g_pmax[((size_t)t * NCHUNK + c) * B + b] - M);
    float lse = M + logf(ss);
    float mask = (target[(t + 1) * B + b] != 0) ? 1.f : 0.f;
    g_lp[t * B + b] = mask * (g_tgtl[t * B + b] - lse);
}

__global__ void k_out(float* __restrict__ out) {
    const int b = threadIdx.x;
    float s = 0.f;
    for (int t = 0; t < TL; t++) s += g_lp[t * B + b];
    out[b] = s;
}

extern "C" void kernel_launch(void* const* d_in, const int* in_sizes, int n_in,
                              void* d_out, int out_size) {
    const int*   source = (const int*)d_in[0];
    const int*   target = (const int*)d_in[1];
    const int*   elen   = (const int*)d_in[2];
    const float* p3  = (const float*)d_in[3];
    const float* p4  = (const float*)d_in[4];
    const float* p5  = (const float*)d_in[5];
    const float* p6  = (const float*)d_in[6];
    const float* p7  = (const float*)d_in[7];
    const float* p8  = (const float*)d_in[8];
    const float* p9  = (const float*)d_in[9];
    const float* p10 = (const float*)d_in[10];
    const float* p11 = (const float*)d_in[11];
    const float* p12 = (const float*)d_in[12];
    const float* p13 = (const float*)d_in[13];
    const float* p14 = (const float*)d_in[14];
    const float* p15 = (const float*)d_in[15];
    const float* p16 = (const float*)d_in[16];
    const float* p17 = (const float*)d_in[17];
    const float* p18 = (const float*)d_in[18];
    const float* p19 = (const float*)d_in[19];
    const float* p20 = (const float*)d_in[20];
    float* out = (float*)d_out;

    cudaFuncSetAttribute(k_encoder, cudaFuncAttributeMaxDynamicSharedMemorySize, 147456);
    cudaFuncSetAttribute(k_Fpre,    cudaFuncAttributeMaxDynamicSharedMemorySize, 98304);
    cudaFuncSetAttribute(k_decoder, cudaFuncAttributeMaxDynamicSharedMemorySize, 149504);
    cudaFuncSetAttribute(k_logits,  cudaFuncAttributeMaxDynamicSharedMemorySize, 98304);

    k_setup<<<64, 256>>>();                                        // 1
    k_embed2<<<dim3(S + T, B), 128>>>(source, target, p3, p4);     // 2
    k_gemm_pre2<<<dim3(32, 56), 256>>>(p5, p7, p11, p13);          // 3
    k_encoder<<<NBLK, 512, 147456>>>(p6, p8, p9, p10);             // 4 (profiled)
    k_Fpre<<<dim3(8, 32), 256, 98304>>>(p19);                      // 5
    k_decoder<<<NBLK, 512, 149504>>>(p11, p12, p14, p15, p16,
                                     p17, p18, p19, elen);         // 6
    k_logits<<<dim3(NCHUNK, TL), 256, 98304>>>(p20, target);       // 7
    k_combine<<<TL, 32>>>(target);                                 // 8
    k_out<<<1, 32>>>(out);                                         // 9
}

// round 14
// speedup vs baseline: 1.0351x; 1.0351x over previous
#include <cuda_runtime.h>
#include <math.h>

#define B   32
#define E   512
#define H   512
#define H4  2048
#define S   64
#define T   48
#define VT  32000
#define TL  (T-1)
#define VB  640
#define NCHUNK (VT/VB)
#define NBLK 128

#define PIDX(h,b) ((((h)>>1)<<6) + ((b)<<1) + ((h)&1))

__device__ __align__(128) float g_x[S*E*B];
__device__ __align__(128) float g_y[T*E*B];
__device__ __align__(128) float g_zx0[S*H4*B];
__device__ __align__(128) float g_zy [T*H4*B];
__device__ __align__(128) float g_h1seq[S*H*B];
__device__ __align__(128) float g_h2seq[S*H*B];
__device__ __align__(128) float g_ebsh[B*S*H];
__device__ __align__(128) float g_ebhs[B*H*S];
__device__ __align__(128) float g_F[B*H*S];
__device__ __align__(128) float g_A[H*B];
__device__ __align__(128) float g_zcy[H*B];
__device__ __align__(128) float g_scores[B*S];
__device__ __align__(128) float g_c0[H*B];
__device__ __align__(128) float g_c1[H*B];
__device__ __align__(128) float g_dh0a[H*B];
__device__ __align__(128) float g_dh0b[H*B];
__device__ __align__(128) float g_dh1a[H*B];
__device__ __align__(128) float g_dh1b[H*B];
__device__ __align__(128) float g_zero[H*B];
__device__ __align__(128) float g_decout[T*H*B];
__device__ __align__(128) float g_pmax[TL*NCHUNK*B];
__device__ __align__(128) float g_psum[TL*NCHUNK*B];
__device__ __align__(128) float g_tgtl[TL*B];
__device__ __align__(128) float g_lp[TL*B];

__device__ __forceinline__ void fma2(unsigned long long& a,
                                     unsigned long long w, unsigned long long u) {
    asm("fma.rn.f32x2 %0, %1, %2, %3;" : "=l"(a) : "l"(w), "l"(u), "l"(a));
}
__device__ __forceinline__ float sum2(unsigned long long v) {
    float lo, hi;
    asm("mov.b64 {%0, %1}, %2;" : "=f"(lo), "=f"(hi) : "l"(v));
    return lo + hi;
}

// ---- tree grid barrier: 8 padded leaf counters (16 arrivals each) -> root(8)
// Counters are MONOTONIC (no reset race). Ordering: each block does
// data-writes -> threadfence -> leaf atomic; atomic RMW chains carry the
// ordering up the tree; the root finisher fences + bumps g_gen.
__device__ unsigned g_leaf[8 * 32];   // one counter per 128B (distinct LTS slices)
__device__ unsigned g_root;
__device__ volatile unsigned g_gen;

__device__ __forceinline__ void gridbar() {
    __syncthreads();
    if (threadIdx.x == 0) {
        unsigned old = g_gen;
        __threadfence();
        unsigned a = atomicAdd(&g_leaf[(blockIdx.x & 7) << 5], 1u);
        bool released = false;
        if ((a & 15) == 15) {                      // 16th arrival in this leaf
            unsigned r = atomicAdd(&g_root, 1u);
            if ((r & 7) == 7) {                    // last leaf escalation
                __threadfence();
                g_gen = old + 1;
                released = true;
            }
        }
        if (!released)
            while (g_gen == old) __nanosleep(64);
        __threadfence();
    }
    __syncthreads();
}

__global__ void k_setup() {
    int i = blockIdx.x * 256 + threadIdx.x;
    if (i < H * B) { g_c0[i] = 0.f; g_c1[i] = 0.f; g_zero[i] = 0.f; }
    if (i < 256) g_leaf[i] = 0u;
    if (i == 0) { g_root = 0u; g_gen = 0u; }
}

__global__ void k_embed2(const int* __restrict__ src, const int* __restrict__ tgt,
                         const float* __restrict__ semb, const float* __restrict__ temb) {
    int n = blockIdx.x, b = blockIdx.y;
    const float* e; float* d;
    if (n < S) { e = semb + (size_t)src[n * B + b] * E; d = g_x + (size_t)n * E * B; }
    else { int m = n - S; e = temb + (size_t)tgt[m * B + b] * E; d = g_y + (size_t)m * E * B; }
    for (int k = threadIdx.x; k < E; k += 128) d[PIDX(k, b)] = e[k];
}

// pre-GEMM, per-chunk staging, 48KB smem -> 4 blocks/SM
__global__ void __launch_bounds__(256) k_gemm_pre(
        const float* __restrict__ W, int ldw, const float* __restrict__ bias,
        const float* __restrict__ U, float* __restrict__ Z) {
    extern __shared__ __align__(16) float smp[];
    float* su = smp;             // 4096 floats (one 128-k chunk, packed)
    float* wt = smp + 4096;      // 64 rows x 128 cols
    const unsigned long long* su2 = (const unsigned long long*)su;
    const int tid = threadIdx.x, lane = tid & 31, warp = tid >> 5;
    const int n = blockIdx.y, o0 = blockIdx.x * 64;
    unsigned long long acc2[8] = {0ull,0ull,0ull,0ull,0ull,0ull,0ull,0ull};
    for (int kc = 0; kc < 4; kc++) {
        __syncthreads();
        {
            const float4* src = (const float4*)(U + ((size_t)n * 512 + kc * 128) * B);
            #pragma unroll
            for (int i = tid; i < 1024; i += 256) ((float4*)su)[i] = src[i];
            #pragma unroll
            for (int q = 0; q < 8; q++) {
                int f4 = q * 256 + tid;
                ((float4*)wt)[f4] = *(const float4*)(
                    W + (size_t)(o0 + (f4 >> 5)) * ldw + kc * 128 + (f4 & 31) * 4);
            }
        }
        __syncthreads();
        #pragma unroll 4
        for (int kk = 0; kk < 128; kk += 4) {
            unsigned long long u01 = su2[(kk >> 1) * 32 + lane];
            unsigned long long u23 = su2[((kk >> 1) + 1) * 32 + lane];
            #pragma unroll
            for (int r = 0; r < 8; r++) {
                ulonglong2 wv = *(const ulonglong2*)(wt + (warp * 8 + r) * 128 + kk);
                fma2(acc2[r], wv.x, u01);
                fma2(acc2[r], wv.y, u23);
            }
        }
    }
    #pragma unroll
    for (int r = 0; r < 8; r++)
        Z[((size_t)n * H4 + o0 + warp * 8 + r) * B + lane] =
            sum2(acc2[r]) + bias[o0 + warp * 8 + r];
}

// LSTM cell (known-good): 2 groups of 8 warps, smem-staged u
template<int HPB>
__device__ __forceinline__ void cellS(
        int blk, const float* __restrict__ zpre, const float* __restrict__ bias,
        const float* sW1, const float* sW2,
        const float* __restrict__ u1, const float* __restrict__ u2,
        float* __restrict__ C, float* __restrict__ Hout, float* su, float* sz) {
    constexpr int NR = 4 * HPB, RPW = NR / 8;
    const int tid = threadIdx.x, lane = tid & 31, w = tid >> 5;
    const int g = w >> 3, wi = w & 7;
    const int h0 = blk * HPB;
    const bool dual = (sW2 != nullptr);
    const float* sW = (dual && g) ? sW2 : sW1;
    const float* u  = (dual && g) ? u2  : u1;
    const int Kbase  = dual ? 0 : g * 256;
    const int nchunk = dual ? 4 : 2;
    float* sbuf = su + g * (128 * B);
    const unsigned long long* sb2 = (const unsigned long long*)sbuf;
    const int gt = tid & 255;
    unsigned long long acc[RPW][2];
    #pragma unroll
    for (int j = 0; j < RPW; j++) { acc[j][0] = 0ull; acc[j][1] = 0ull; }
    for (int c = 0; c < nchunk; c++) {
        const float4* src = (const float4*)(u + (size_t)(Kbase + c * 128) * B);
        float4* dst = (float4*)sbuf;
        #pragma unroll
        for (int q = 0; q < 4; q++) dst[gt + 256 * q] = src[gt + 256 * q];
        __syncthreads();
        const int kofs = Kbase + c * 128;
        #pragma unroll 8
        for (int kk = 0; kk < 128; kk += 4) {
            unsigned long long u01 = sb2[(kk >> 1) * 32 + lane];
            unsigned long long u23 = sb2[(kk >> 1) * 32 + 32 + lane];
            #pragma unroll
            for (int j = 0; j < RPW; j++) {
                int r = wi * RPW + j;
                ulonglong2 wv = *(const ulonglong2*)(sW + r * 512 + kofs + kk);
                fma2(acc[j][0], wv.x, u01);
                fma2(acc[j][1], wv.y, u23);
            }
        }
        __syncthreads();
    }
    #pragma unroll
    for (int j = 0; j < RPW; j++) {
        int r = wi * RPW + j;
        int o = (r / HPB) * H + h0 + (r % HPB);
        float v = sum2(acc[j][0]) + sum2(acc[j][1]);
        if (g == 0) v += zpre ? zpre[(size_t)o * B + lane] : bias[o];
        sz[(g * NR + r) * 32 + lane] = v;
    }
    __syncthreads();
    if (tid < HPB * 32) {
        int hh = tid >> 5, b = tid & 31;
        float z[4];
        #pragma unroll
        for (int jg = 0; jg < 4; jg++) {
            int r = jg * HPB + hh;
            z[jg] = sz[r * 32 + b] + sz[(NR + r) * 32 + b];
        }
        float ig = 1.f / (1.f + expf(-z[0]));
        float fg = 1.f / (1.f + expf(-z[1]));
        float gg = tanhf(z[2]);
        float og = 1.f / (1.f + expf(-z[3]));
        int h = h0 + hh;
        float c2 = fg * C[h * B + b] + ig * gg;
        C[h * B + b]     = c2;
        Hout[PIDX(h, b)] = og * tanhf(c2);
    }
    __syncthreads();
}

__global__ void __launch_bounds__(512) k_encoder(
        const float* __restrict__ eWhh0, const float* __restrict__ eWih1,
        const float* __restrict__ eWhh1, const float* __restrict__ eb1) {
    extern __shared__ __align__(16) float sm[];
    float* su = sm;
    float* sz = sm + 8192;
    float* sw = sm + 10240;
    const int blk = blockIdx.x, tid = threadIdx.x;
    if (blk < 64) {
        for (int i = tid; i < 32 * 128; i += 512) {
            int r = i >> 7, c4 = i & 127;
            int o = (r >> 3) * H + blk * 8 + (r & 7);
            ((float4*)sw)[i] = *(const float4*)(eWhh0 + (size_t)o * H + c4 * 4);
        }
    } else {
        int b2 = blk - 64;
        for (int i = tid; i < 32 * 128; i += 512) {
            int r = i >> 7, c4 = i & 127;
            int o = (r >> 3) * H + b2 * 8 + (r & 7);
            ((float4*)sw)[i]           = *(const float4*)(eWih1 + (size_t)o * H + c4 * 4);
            ((float4*)(sw + 16384))[i] = *(const float4*)(eWhh1 + (size_t)o * H + c4 * 4);
        }
    }
    __syncthreads();
    for (int p = 0; p <= S; p++) {
        if (p < S && blk < 64) {
            const float* hp = p ? g_h1seq + (size_t)(p - 1) * H * B : g_zero;
            cellS<8>(blk, g_zx0 + (size_t)p * H4 * B, nullptr, sw, nullptr,
                     hp, nullptr, g_c0, g_h1seq + (size_t)p * H * B, su, sz);
        } else if (p >= 1 && blk >= 64) {
            int s = p - 1;
            const float* hp = s ? g_h2seq + (size_t)(s - 1) * H * B : g_zero;
            cellS<8>(blk - 64, nullptr, eb1, sw, sw + 16384,
                     g_h1seq + (size_t)s * H * B, hp,
                     g_c1, g_h2seq + (size_t)s * H * B, su, sz);
        }
        gridbar();
    }
    for (int idx = blk; idx < S * B; idx += NBLK) {
        int s = idx >> 5, b = idx & 31;
        for (int h = tid; h < H; h += 512) {
            float v = g_h2seq[(size_t)s * H * B + PIDX(h, b)];
            g_ebsh[((size_t)b * S + s) * H + h] = v;
            g_ebhs[((size_t)b * H + h) * S + s] = v;
        }
    }
}

// F[b,h,s] = sum_k Wct[h,k] * ebhs[b,k,s]
__global__ void __launch_bounds__(256) k_Fpre(const float* __restrict__ Wct) {
    extern __shared__ __align__(16) float smf[];
    float* se  = smf;
    float* swd = smf + 8192;
    const unsigned long long* se2  = (const unsigned long long*)se;
    const unsigned long long* swd2 = (const unsigned long long*)swd;
    const int tid = threadIdx.x, lane = tid & 31, w = tid >> 5;
    const int hc = blockIdx.x, b = blockIdx.y;
    unsigned long long acc2[8] = {0ull,0ull,0ull,0ull,0ull,0ull,0ull,0ull};
    for (int kc = 0; kc < 4; kc++) {
        __syncthreads();
        {
            const float4* src = (const float4*)(g_ebhs + ((size_t)b * H + kc * 128) * S);
            #pragma unroll
            for (int i = tid; i < 2048; i += 256) ((float4*)se)[i] = src[i];
            #pragma unroll
            for (int i4 = tid; i4 < 2048; i4 += 256) {
                int row = i4 >> 5, c4 = i4 & 31;
                float4 v = *(const float4*)(Wct + (size_t)(hc * 64 + row) * 1024 + kc * 128 + c4 * 4);
                float2* dp = (float2*)(swd + (row * 128 + c4 * 4) * 2);
                dp[0] = make_float2(v.x, v.x); dp[1] = make_float2(v.y, v.y);
                dp[2] = make_float2(v.z, v.z); dp[3] = make_float2(v.w, v.w);
            }
        }
        __syncthreads();
        #pragma unroll 4
        for (int kk = 0; kk < 128; kk++) {
            unsigned long long u = se2[kk * 32 + lane];
            #pragma unroll
            for (int r = 0; r < 8; r++)
                fma2(acc2[r], swd2[(w * 8 + r) * 128 + kk], u);
        }
    }
    #pragma unroll
    for (int r = 0; r < 8; r++) {
        int h = hc * 64 + w * 8 + r;
        ((unsigned long long*)(g_F + ((size_t)b * H + h) * S))[lane] = acc2[r];
    }
}

__global__ void __launch_bounds__(512) k_decoder(
        const float* __restrict__ dWih0, const float* __restrict__ dWhh0,
        const float* __restrict__ dWih1, const float* __restrict__ dWhh1,
        const float* __restrict__ db1,
        const float* __restrict__ Wht, const float* __restrict__ Wpt,
        const float* __restrict__ Wct, const int* __restrict__ elen) {
    extern __shared__ __align__(16) float sm[];
    float* su  = sm;            // 16384 (cellS uses first 8192; P3 stages 16384)
    float* sz  = sm + 16384;    // 1024
    float* sWa = sm + 17408;    // 4 x 8192
    float* sWb = sWa + 8192;
    float* sWc = sWb + 8192;
    float* sWd = sWc + 8192;
    float* sy  = sWd + 8192;    // 512
    __shared__ float s_at[S];
    __shared__ float s_red[20];
    const int blk = blockIdx.x, tid = threadIdx.x, lane = tid & 31, w = tid >> 5;
    const unsigned long long* su2 = (const unsigned long long*)su;
    for (int i = tid; i < 2048; i += 512) {
        int r = i >> 7, c4 = i & 127;
        int o = (r >> 2) * H + blk * 4 + (r & 3);
        ((float4*)sWa)[i] = *(const float4*)(dWih0 + (size_t)o * (E + H) + E + c4 * 4);
        ((float4*)sWb)[i] = *(const float4*)(dWhh0 + (size_t)o * H + c4 * 4);
        ((float4*)sWc)[i] = *(const float4*)(dWih1 + (size_t)o * H + c4 * 4);
        ((float4*)sWd)[i] = *(const float4*)(dWhh1 + (size_t)o * H + c4 * 4);
    }
    __syncthreads();
    for (int t = 0; t < T; t++) {
        const float* htp = t ? g_decout + (size_t)(t - 1) * H * B : g_zero;
        const float* h0p = t ? (((t - 1) & 1) ? g_dh0b : g_dh0a)
                             : g_h1seq + (size_t)(S - 1) * H * B;
        float* h0c = (t & 1) ? g_dh0b : g_dh0a;
        cellS<4>(blk, g_zy + (size_t)t * H4 * B, nullptr, sWa, sWb,
                 htp, h0p, g_c0, h0c, su, sz);
        gridbar();
        const float* h1p = t ? (((t - 1) & 1) ? g_dh1b : g_dh1a)
                             : g_h2seq + (size_t)(S - 1) * H * B;
        float* h1c = (t & 1) ? g_dh1b : g_dh1a;
        cellS<4>(blk, nullptr, db1, sWc, sWd, h0c, h1p, g_c1, h1c, su, sz);
        gridbar();
        // P3: distributed GEMV (A rows + zcy rows) + scores on blocks 0-31
        {
            const float4* src = (const float4*)h1c;
            #pragma unroll
            for (int i = tid; i < 4096; i += 512) ((float4*)su)[i] = src[i];
            if (blk < B) sy[tid] = h1c[PIDX(tid, blk)];
            __syncthreads();
            {
                int j = w >> 1, khalf = w & 1;
                int rid = blk * 8 + j;
                const float* Wrow = (rid < 512) ? (Wht + (size_t)rid * 512)
                                                : (Wct + (size_t)(rid - 512) * 1024 + 512);
                unsigned long long a0 = 0ull, a1 = 0ull;
                const int kb2 = khalf * 128;
                #pragma unroll 8
                for (int kk = 0; kk < 256; kk += 4) {
                    unsigned long long u01 = su2[(kb2 + (kk >> 1)) * 32 + lane];
                    unsigned long long u23 = su2[(kb2 + (kk >> 1) + 1) * 32 + lane];
                    ulonglong2 wv = *(const ulonglong2*)(Wrow + khalf * 256 + kk);
                    fma2(a0, wv.x, u01);
                    fma2(a1, wv.y, u23);
                }
                sz[w * 32 + lane] = sum2(a0) + sum2(a1);
            }
            __syncthreads();
            if (tid < 256) {
                int jj = tid >> 5, b = tid & 31;
                int rr = blk * 8 + jj;
                float v = sz[(2 * jj) * 32 + b] + sz[(2 * jj + 1) * 32 + b];
                if (rr < 512) g_A[rr * 32 + b] = Wpt[rr] * tanhf(v);
                else          g_zcy[(rr - 512) * 32 + b] = v;
            }
            if (blk < B) {
                int b = blk, el = elen[b];
                float4 uk[4];
                #pragma unroll
                for (int qq = 0; qq < 4; qq++) uk[qq] = *(const float4*)(sy + qq * 128 + lane * 4);
                #pragma unroll
                for (int si = 0; si < 4; si++) {
                    int s = w * 4 + si;
                    const float* er = g_ebsh + ((size_t)b * S + s) * H;
                    float v = 0.f;
                    #pragma unroll
                    for (int qq = 0; qq < 4; qq++) {
                        float4 ev = *(const float4*)(er + qq * 128 + lane * 4);
                        v += ev.x*uk[qq].x + ev.y*uk[qq].y + ev.z*uk[qq].z + ev.w*uk[qq].w;
                    }
                    #pragma unroll
                    for (int off = 16; off; off >>= 1)
                        v += __shfl_xor_sync(0xffffffffu, v, off);
                    if (lane == 0) g_scores[b * S + s] = (s < el) ? v : -INFINITY;
                }
            }
        }
        gridbar();
        // P4: pt + softmax*gauss + decout (blocks 0-31)
        if (blk < B) {
            int b = blk;
            float a = g_A[tid * 32 + b];
            #pragma unroll
            for (int off = 16; off; off >>= 1) a += __shfl_xor_sync(0xffffffffu, a, off);
            if (lane == 0) s_red[w] = a;
            __syncthreads();
            if (tid == 0) {
                float dd = 0.f;
                #pragma unroll
                for (int i = 0; i < 16; i++) dd += s_red[i];
                s_red[16] = (1.f / (1.f + expf(-dd))) * (float)elen[b];
            }
            __syncthreads();
            if (w == 0) {
                float pt = s_red[16];
                float v0 = g_scores[b * S + lane], v1 = g_scores[b * S + lane + 32];
                float mx = fmaxf(v0, v1);
                #pragma unroll
                for (int off = 16; off; off >>= 1)
                    mx = fmaxf(mx, __shfl_xor_sync(0xffffffffu, mx, off));
                float e0 = expf(v0 - mx), e1 = expf(v1 - mx);
                float smv = e0 + e1;
                #pragma unroll
                for (int off = 16; off; off >>= 1)
                    smv += __shfl_xor_sync(0xffffffffu, smv, off);
                float inv = 1.f / smv;
                float d0 = (float)lane - pt, d1 = (float)(lane + 32) - pt;
                s_at[lane]      = e0 * inv * expf(-d0 * d0 * (1.f / 50.f));
                s_at[lane + 32] = e1 * inv * expf(-d1 * d1 * (1.f / 50.f));
            }
            __syncthreads();
            {
                int h = tid;
                float f = g_zcy[h * 32 + b];
                const float4* Fr = (const float4*)(g_F + ((size_t)b * H + h) * S);
                #pragma unroll
                for (int s4 = 0; s4 < 16; s4++) {
                    float4 fv = Fr[s4];
                    f += s_at[s4*4+0]*fv.x + s_at[s4*4+1]*fv.y
                       + s_at[s4*4+2]*fv.z + s_at[s4*4+3]*fv.w;
                }
                g_decout[(size_t)t * H * B + PIDX(h, b)] = tanhf(f);
            }
        }
        gridbar();
    }
}

__global__ void __launch_bounds__(256) k_logits(const float* __restrict__ Wf,
                                                const int* __restrict__ target) {
    extern __shared__ __align__(16) float sm_[];
    float* sdec = sm_;
    float* wt   = sm_ + 512 * B;
    const unsigned long long* sd2 = (const unsigned long long*)sdec;
    __shared__ float rm[8][32], rs[8][32];
    const int t = blockIdx.y, c = blockIdx.x;
    const int tid = threadIdx.x, lane = tid & 31, warp = tid >> 5;
    {
        const float4* src = (const float4*)&g_decout[(size_t)t * H * B];
        #pragma unroll
        for (int i = tid; i < H * B / 4; i += 256) ((float4*)sdec)[i] = src[i];
    }
    __syncthreads();
    const int tgt = target[(t + 1) * B + lane];
    float m = -INFINITY, ss = 0.f;
    for (int rt = 0; rt < 10; rt++) {
        const int r0 = c * VB + rt * 64;
        unsigned long long acc2[8] = {0ull,0ull,0ull,0ull,0ull,0ull,0ull,0ull};
        for (int kc = 0; kc < 4; kc++) {
            __syncthreads();
            #pragma unroll
            for (int q = 0; q < 8; q++) {
                int f4 = q * 256 + tid;
                ((float4*)wt)[f4] = *(const float4*)(
                    Wf + (size_t)(r0 + (f4 >> 5)) * H + kc * 128 + (f4 & 31) * 4);
            }
            __syncthreads();
            const unsigned long long* ub2 = sd2 + kc * 2048;
            #pragma unroll 4
            for (int kk = 0; kk < 128; kk += 4) {
                unsigned long long u01 = ub2[(kk >> 1) * 32 + lane];
                unsigned long long u23 = ub2[(kk >> 1) * 32 + 32 + lane];
                #pragma unroll
                for (int r = 0; r < 8; r++) {
                    ulonglong2 wv = *(const ulonglong2*)(wt + (warp * 8 + r) * 128 + kk);
                    fma2(acc2[r], wv.x, u01);
                    fma2(acc2[r], wv.y, u23);
                }
            }
        }
        #pragma unroll
        for (int r = 0; r < 8; r++) {
            float x = sum2(acc2[r]);
            if (r0 + warp * 8 + r == tgt) g_tgtl[t * B + lane] = x;
            float nm = fmaxf(m, x);
            ss = ss * expf(m - nm) + expf(x - nm);
            m = nm;
        }
    }
    rm[warp][lane] = m; rs[warp][lane] = ss;
    __syncthreads();
    if (tid < 32) {
        float M = -INFINITY, SS = 0.f;
        #pragma unroll
        for (int w2 = 0; w2 < 8; w2++) {
            float wm = rm[w2][tid], wss = rs[w2][tid];
            float nm = fmaxf(M, wm);
            SS = SS * expf(M - nm) + wss * expf(wm - nm);
            M = nm;
        }
        g_pmax[((size_t)t * NCHUNK + c) * B + tid] = M;
        g_psum[((size_t)t * NCHUNK + c) * B + tid] = SS;
    }
}

__global__ void k_combine(const int* __restrict__ target) {
    const int t = blockIdx.x, b = threadIdx.x;
    float M = -INFINITY;
    for (int c = 0; c < NCHUNK; c++)
        M = fmaxf(M, g_pmax[((size_t)t * NCHUNK + c) * B + b]);
    float ss = 0.f;
    for (int c = 0; c < NCHUNK; c++)
        ss += g_psum[((size_t)t * NCHUNK + c) * B + b] *
              expf(g_pmax[((size_t)t * NCHUNK + c) * B + b] - M);
    float lse = M + logf(ss);
    float mask = (target[(t + 1) * B + b] != 0) ? 1.f : 0.f;
    g_lp[t * B + b] = mask * (g_tgtl[t * B + b] - lse);
}

__global__ void k_out(float* __restrict__ out) {
    const int b = threadIdx.x;
    float s = 0.f;
    for (int t = 0; t < TL; t++) s += g_lp[t * B + b];
    out[b] = s;
}

extern "C" void kernel_launch(void* const* d_in, const int* in_sizes, int n_in,
                              void* d_out, int out_size) {
    const int*   source = (const int*)d_in[0];
    const int*   target = (const int*)d_in[1];
    const int*   elen   = (const int*)d_in[2];
    const float* p3  = (const float*)d_in[3];
    const float* p4  = (const float*)d_in[4];
    const float* p5  = (const float*)d_in[5];
    const float* p6  = (const float*)d_in[6];
    const float* p7  = (const float*)d_in[7];
    const float* p8  = (const float*)d_in[8];
    const float* p9  = (const float*)d_in[9];
    const float* p10 = (const float*)d_in[10];
    const float* p11 = (const float*)d_in[11];
    const float* p12 = (const float*)d_in[12];
    const float* p13 = (const float*)d_in[13];
    const float* p14 = (const float*)d_in[14];
    const float* p15 = (const float*)d_in[15];
    const float* p16 = (const float*)d_in[16];
    const float* p17 = (const float*)d_in[17];
    const float* p18 = (const float*)d_in[18];
    const float* p19 = (const float*)d_in[19];
    const float* p20 = (const float*)d_in[20];
    float* out = (float*)d_out;

    float *x, *y, *zx0, *zy;
    cudaGetSymbolAddress((void**)&x,   g_x);
    cudaGetSymbolAddress((void**)&y,   g_y);
    cudaGetSymbolAddress((void**)&zx0, g_zx0);
    cudaGetSymbolAddress((void**)&zy,  g_zy);

    cudaFuncSetAttribute(k_gemm_pre, cudaFuncAttributeMaxDynamicSharedMemorySize, 49152);
    cudaFuncSetAttribute(k_encoder,  cudaFuncAttributeMaxDynamicSharedMemorySize, 172032);
    cudaFuncSetAttribute(k_Fpre,     cudaFuncAttributeMaxDynamicSharedMemorySize, 98304);
    cudaFuncSetAttribute(k_decoder,  cudaFuncAttributeMaxDynamicSharedMemorySize, 202752);
    cudaFuncSetAttribute(k_logits,   cudaFuncAttributeMaxDynamicSharedMemorySize, 98304);

    k_setup<<<64, 256>>>();                                           // 1
    k_embed2<<<dim3(S + T, B), 128>>>(source, target, p3, p4);        // 2
    k_gemm_pre<<<dim3(32, T), 256, 49152>>>(p11, E + H, p13, y, zy);  // 3
    k_gemm_pre<<<dim3(32, S), 256, 49152>>>(p5, E, p7, x, zx0);       // 4
    k_encoder<<<NBLK, 512, 172032>>>(p6, p8, p9, p10);                // 5
    k_Fpre<<<dim3(8, 32), 256, 98304>>>(p19);                         // 6
    k_decoder<<<NBLK, 512, 202752>>>(p11, p12, p14, p15, p16,
                                     p17, p18, p19, elen);            // 7
    k_logits<<<dim3(NCHUNK, TL), 256, 98304>>>(p20, target);          // 8
    k_combine<<<TL, 32>>>(target);                                    // 9
    k_out<<<1, 32>>>(out);                                            // 10
}